// round 13
// baseline (speedup 1.0000x reference)
#include <cuda_runtime.h>
#include <cuda_fp16.h>
#include <math.h>
#include <stdint.h>

#define D       128
#define NHEADS  4
#define MAXN    50048
#define MAXE    640000
#define MAXR    256
#define LAYERS  2

// fp16 dual GEMM: CTA tile M=64, N=256, A via cp.async from fp16 x image.
#define DSTR 68
#define DA_WORDS (2*64*DSTR)
#define DB_WORDS (256*DSTR)
#define MMA_SMEM ((DA_WORDS + DB_WORDS)*4)    // 104448 -> 2 CTAs/SM

// fp16 proj GEMM: CTA tile M=64, N=128, K=320 in 5 chunks of 64
#define PSTR 36
#define PM_A_WORDS (2*64*PSTR)
#define PM_B_WORDS (2*128*PSTR)
#define PM_SMEM ((PM_A_WORDS + PM_B_WORDS)*4) // 55296

// ---------------- helpers ----------------
__device__ __forceinline__ void cp_async16(unsigned saddr, const void* gaddr, int valid) {
    asm volatile("cp.async.ca.shared.global [%0], [%1], 16, %2;"
                 :: "r"(saddr), "l"(gaddr), "r"(valid ? 16 : 0));
}
__device__ __forceinline__ void cp_commit() { asm volatile("cp.async.commit_group;"); }
__device__ __forceinline__ void cp_wait0()  { asm volatile("cp.async.wait_group 0;"); }

__device__ __forceinline__ uint2 ldnc2u(const uint32_t* p) {
    uint2 v;
    asm volatile("ld.global.nc.L1::no_allocate.v2.u32 {%0,%1}, [%2];"
                 : "=r"(v.x), "=r"(v.y) : "l"(p));
    return v;
}

__device__ __forceinline__ uint32_t f2h2(float lo, float hi) {
    __half2 h = __floats2half2_rn(lo, hi);
    return *(uint32_t*)&h;
}
__device__ __forceinline__ float2 h22f2(uint32_t w) {
    return __half22float2(*(__half2*)&w);
}
__device__ __forceinline__ __half2 u2h(uint32_t w) { return *(__half2*)&w; }
__device__ __forceinline__ uint32_t h2u(__half2 h) { return *(uint32_t*)&h; }

// m16n8k16 fp16 MMA, fp32 accumulate
__device__ __forceinline__ void mma_f16(float* d, const uint32_t* a, uint32_t b0, uint32_t b1) {
    asm volatile(
        "mma.sync.aligned.m16n8k16.row.col.f32.f16.f16.f32 "
        "{%0,%1,%2,%3}, {%4,%5,%6,%7}, {%8,%9}, {%0,%1,%2,%3};"
        : "+f"(d[0]), "+f"(d[1]), "+f"(d[2]), "+f"(d[3])
        : "r"(a[0]), "r"(a[1]), "r"(a[2]), "r"(a[3]), "r"(b0), "r"(b1));
}

// ---------------- device scratch ----------------
__device__ uint32_t g_xlh[MAXN*64];           // fp16 x_l image [n][64 half2-words]
__device__ float    g_xr[MAXN*D];
__device__ uint32_t g_xh[MAXN*64];            // fp16 x image (GEMM A operand)
__device__ int      g_rowptr[MAXN+1];
__device__ int      g_woff[MAXN];
__device__ int      g_adj[MAXE];
__device__ int      g_partials[128];
__device__ uint32_t g_relh[LAYERS*MAXR*64];   // fp16 relproj image
__device__ uint32_t g_bstage[LAYERS*256*64];
__device__ uint32_t g_bproj[128*160];

// ---------------- CSR build ----------------
__global__ void hist_kernel(const int* __restrict__ dst, int* cnt, int e) {
    int i = blockIdx.x*blockDim.x + threadIdx.x;
    if (i < e) atomicAdd(&cnt[dst[i]], 1);
}

__global__ void scan1_kernel(const int* __restrict__ cnt, int* rowptr, int* partials, int n) {
    __shared__ int sh[1024];
    int i = blockIdx.x*1024 + threadIdx.x;
    int v = (i < n) ? cnt[i] : 0;
    sh[threadIdx.x] = v;
    __syncthreads();
    for (int off = 1; off < 1024; off <<= 1) {
        int t = (threadIdx.x >= off) ? sh[threadIdx.x - off] : 0;
        __syncthreads();
        sh[threadIdx.x] += t;
        __syncthreads();
    }
    if (i < n) rowptr[i] = sh[threadIdx.x] - v;
    if (threadIdx.x == 1023) partials[blockIdx.x] = sh[1023];
}

__global__ void scan2_kernel(int* partials, int* rowptr, int nb, int n, int total) {
    __shared__ int sh[128];
    int v = (threadIdx.x < nb) ? partials[threadIdx.x] : 0;
    sh[threadIdx.x] = v;
    __syncthreads();
    for (int off = 1; off < 128; off <<= 1) {
        int t = (threadIdx.x >= off) ? sh[threadIdx.x - off] : 0;
        __syncthreads();
        sh[threadIdx.x] += t;
        __syncthreads();
    }
    if (threadIdx.x < nb) partials[threadIdx.x] = sh[threadIdx.x] - v;
    if (threadIdx.x == 0) rowptr[n] = total;
}

__global__ void scan3_kernel(int* rowptr, const int* __restrict__ partials, int* woff, int n) {
    int i = blockIdx.x*blockDim.x + threadIdx.x;
    if (i < n) {
        int v = rowptr[i] + partials[i >> 10];
        rowptr[i] = v;
        woff[i] = v;
    }
}

__global__ void scatter_kernel(const int* __restrict__ src, const int* __restrict__ dst,
                               const int* __restrict__ etype, int* woff, int* adj, int e) {
    int i = blockIdx.x*blockDim.x + threadIdx.x;
    if (i < e) {
        int p = atomicAdd(&woff[dst[i]], 1);
        adj[p] = src[i] | (etype[i] << 20);
    }
}

// ---------------- rel_proj -> fp16 image ----------------
__global__ void relproj_kernel(const float* __restrict__ rel, const float* __restrict__ we,
                               uint32_t* __restrict__ outp, int Rn) {
    int r0 = blockIdx.x * 4, l = blockIdx.y, c2 = threadIdx.x;  // c2: 0..63
    __shared__ float sr[4][D];
#pragma unroll
    for (int j = 0; j < 8; j++) {
        int q = j*64 + c2;
        int row = q >> 7, ch = q & 127;
        int rr = r0 + row;
        sr[row][ch] = (rr < Rn) ? rel[rr*D + ch] : 0.f;
    }
    __syncthreads();
    const float* W = we + l*D*D;
    float a[4][2];
#pragma unroll
    for (int j = 0; j < 4; j++) { a[j][0] = 0.f; a[j][1] = 0.f; }
#pragma unroll 8
    for (int k = 0; k < D; k++) {
        float w0 = __ldg(&W[k*D + 2*c2]);
        float w1 = __ldg(&W[k*D + 2*c2 + 1]);
#pragma unroll
        for (int j = 0; j < 4; j++) {
            a[j][0] = fmaf(sr[j][k], w0, a[j][0]);
            a[j][1] = fmaf(sr[j][k], w1, a[j][1]);
        }
    }
#pragma unroll
    for (int j = 0; j < 4; j++)
        if (r0 + j < Rn)
            outp[(l*Rn + r0 + j)*64 + c2] = f2h2(a[j][0], a[j][1]);
}

// ---------------- B pre-stages (fp16 pairs) ----------------
__global__ void prep_b_kernel(const float* __restrict__ wl, const float* __restrict__ wr,
                              uint32_t* __restrict__ gB) {
    int nrow = blockIdx.x, l = blockIdx.y, kw = threadIdx.x;
    int c = nrow & 127;
    const float* W = (nrow < 128) ? (wl + l*D*D) : (wr + l*D*D);
    gB[l*16384 + nrow*64 + kw] = f2h2(W[(2*kw)*D + c], W[(2*kw+1)*D + c]);
}

__global__ void prep_bp_kernel(const float* __restrict__ pw, uint32_t* __restrict__ gBp, int F) {
    int nrow = blockIdx.x;
    int kw = threadIdx.x;
    float v0 = (2*kw     < F) ? pw[(2*kw)*128 + nrow]     : 0.f;
    float v1 = (2*kw + 1 < F) ? pw[(2*kw + 1)*128 + nrow] : 0.f;
    gBp[nrow*160 + kw] = f2h2(v0, v1);
}

// ---------------- fp16 proj GEMM -> writes fp16 x image ----------------
__global__ __launch_bounds__(256, 2) void proj_mma_kernel(
    const float* __restrict__ nf, const int* __restrict__ entity,
    const uint32_t* __restrict__ gBp, const float* __restrict__ pb,
    uint32_t* __restrict__ xh, int n, int F, int nTiles) {
    extern __shared__ uint32_t smu[];
    uint32_t* AsU = smu;
    uint32_t* BsU = smu + PM_A_WORDS;
    int tid = threadIdx.x, lane = tid & 31, wid = tid >> 5;
    int wm = wid >> 2, wn = wid & 3;
    int lr = lane >> 2, lc = lane & 3;

    unsigned bbase = (unsigned)__cvta_generic_to_shared(BsU);

    float bjx[4], bjy[4];
#pragma unroll
    for (int nt = 0; nt < 4; nt++) {
        int col = wn*32 + nt*8 + 2*lc;
        bjx[nt] = pb[col];
        bjy[nt] = pb[col+1];
    }

    float4 aReg[4];
    auto loadA = [&](int t, int c) {
#pragma unroll
        for (int j = 0; j < 4; j++) {
            int q = tid + j*256;
            int r = q >> 4, k4 = q & 15;
            int gr = t*64 + r;
            int kg = c*64 + k4*4;
            aReg[j] = (gr < n && kg < F)
                ? *(const float4*)&nf[(long long)entity[gr]*F + kg]
                : make_float4(0,0,0,0);
        }
    };
    auto stsA = [&](int buf) {
#pragma unroll
        for (int j = 0; j < 4; j++) {
            int q = tid + j*256;
            int r = q >> 4, k4 = q & 15;
            uint2 w = make_uint2(f2h2(aReg[j].x, aReg[j].y), f2h2(aReg[j].z, aReg[j].w));
            *(uint2*)&AsU[buf*64*PSTR + r*PSTR + k4*2] = w;
        }
    };
    auto issueB = [&](int c, int buf) {
#pragma unroll
        for (int j = 0; j < 4; j++) {
            int q = tid + j*256;
            int row = q >> 3, seg = q & 7;
            cp_async16(bbase + (buf*128*PSTR + row*PSTR + seg*4)*4,
                       gBp + row*160 + c*32 + seg*4, 1);
        }
        cp_commit();
    };

    int tile0 = blockIdx.x;
    loadA(tile0, 0);
    issueB(0, 0);
    stsA(0);
    cp_wait0();
    __syncthreads();

    int buf = 0;
    for (int t = tile0; t < nTiles; t += gridDim.x) {
        float acc[2][4][4];
#pragma unroll
        for (int mt = 0; mt < 2; mt++)
#pragma unroll
            for (int nt = 0; nt < 4; nt++)
#pragma unroll
                for (int i = 0; i < 4; i++) acc[mt][nt][i] = 0.f;

#pragma unroll
        for (int c = 0; c < 5; c++) {
            int tn = (c < 4) ? t : t + gridDim.x;
            int cn = (c < 4) ? c + 1 : 0;
            bool hasNext = (c < 4) || (tn < nTiles);
            if (hasNext) { loadA(tn, cn); issueB(cn, buf ^ 1); }

            const uint32_t* Ab = &AsU[buf*64*PSTR];
            const uint32_t* Bb = &BsU[buf*128*PSTR];
#pragma unroll
            for (int kk = 0; kk < 4; kk++) {
                int kw0 = kk*8;
                uint32_t a[2][4];
#pragma unroll
                for (int mt = 0; mt < 2; mt++) {
                    int r = wm*32 + mt*16 + lr;
                    a[mt][0] = Ab[r*PSTR + kw0 + lc];
                    a[mt][1] = Ab[(r+8)*PSTR + kw0 + lc];
                    a[mt][2] = Ab[r*PSTR + kw0 + lc + 4];
                    a[mt][3] = Ab[(r+8)*PSTR + kw0 + lc + 4];
                }
#pragma unroll
                for (int nt = 0; nt < 4; nt++) {
                    int nrow = wn*32 + nt*8 + lr;
                    uint32_t b0 = Bb[nrow*PSTR + kw0 + lc];
                    uint32_t b1 = Bb[nrow*PSTR + kw0 + lc + 4];
                    mma_f16(acc[0][nt], a[0], b0, b1);
                    mma_f16(acc[1][nt], a[1], b0, b1);
                }
            }

            if (c == 4) {
#pragma unroll
                for (int mt = 0; mt < 2; mt++) {
                    int r1 = t*64 + wm*32 + mt*16 + lr;
#pragma unroll
                    for (int nt = 0; nt < 4; nt++) {
                        int col = wn*32 + nt*8 + 2*lc;
                        if (r1 < n)
                            xh[(size_t)r1*64 + (col>>1)] =
                                f2h2(acc[mt][nt][0] + bjx[nt], acc[mt][nt][1] + bjy[nt]);
                        if (r1 + 8 < n)
                            xh[(size_t)(r1+8)*64 + (col>>1)] =
                                f2h2(acc[mt][nt][2] + bjx[nt], acc[mt][nt][3] + bjy[nt]);
                    }
                }
            }

            if (hasNext) stsA(buf ^ 1);
            cp_wait0();
            __syncthreads();
            buf ^= 1;
        }
    }
}

// ---------------- fp16 dual GEMM: CTA 64x256, A via cp.async from xh ----------------
__global__ __launch_bounds__(256, 2) void gemm_dual_mma_kernel(
    const uint32_t* __restrict__ xh, const uint32_t* __restrict__ gB,
    const float* __restrict__ bl, const float* __restrict__ br,
    uint32_t* __restrict__ xlh, float* __restrict__ outr, int n, int nTiles) {
    extern __shared__ uint32_t smu[];
    uint32_t* AsU = smu;
    uint32_t* BsU = smu + DA_WORDS;
    int tid = threadIdx.x, lane = tid & 31, wid = tid >> 5;
    int wm = wid >> 2, wn = wid & 3;
    int lr = lane >> 2, lc = lane & 3;

    unsigned abase = (unsigned)__cvta_generic_to_shared(AsU);

    {
        unsigned bbase = (unsigned)__cvta_generic_to_shared(BsU);
#pragma unroll
        for (int j = 0; j < 16; j++) {
            int q = tid + j*256;
            int row = q >> 4, seg = q & 15;
            cp_async16(bbase + (row*DSTR + seg*4)*4, gB + row*64 + seg*4, 1);
        }
    }

    auto issueA = [&](int t, int buf) {
#pragma unroll
        for (int j = 0; j < 4; j++) {
            int q = tid + j*256;
            int row = q >> 4, seg = q & 15;
            cp_async16(abase + (buf*64*DSTR + row*DSTR + seg*4)*4,
                       xh + (size_t)(t*64 + row)*64 + seg*4, 1);
        }
        cp_commit();
    };

    float bjx[8], bjy[8];
#pragma unroll
    for (int nt = 0; nt < 8; nt++) {
        int col = wn*64 + nt*8 + 2*lc;
        const float* bv = (col < 128) ? bl : br;
        int c = col & 127;
        bjx[nt] = bv[c];
        bjy[nt] = bv[c+1];
    }

    int tile0 = blockIdx.x;
    issueA(tile0, 0);
    cp_wait0();
    __syncthreads();

    int buf = 0;
    for (int t = tile0; t < nTiles; t += gridDim.x, buf ^= 1) {
        int tn = t + gridDim.x;
        if (tn < nTiles) issueA(tn, buf ^ 1);

        float acc[2][8][4];
#pragma unroll
        for (int mt = 0; mt < 2; mt++)
#pragma unroll
            for (int nt = 0; nt < 8; nt++)
#pragma unroll
                for (int i = 0; i < 4; i++) acc[mt][nt][i] = 0.f;

        const uint32_t* Ab = &AsU[buf*64*DSTR];
#pragma unroll
        for (int kk = 0; kk < 8; kk++) {
            int kw0 = kk*8;
            uint32_t a[2][4];
#pragma unroll
            for (int mt = 0; mt < 2; mt++) {
                int r = wm*32 + mt*16 + lr;
                a[mt][0] = Ab[r*DSTR + kw0 + lc];
                a[mt][1] = Ab[(r+8)*DSTR + kw0 + lc];
                a[mt][2] = Ab[r*DSTR + kw0 + lc + 4];
                a[mt][3] = Ab[(r+8)*DSTR + kw0 + lc + 4];
            }
#pragma unroll
            for (int nt = 0; nt < 8; nt++) {
                int nrow = wn*64 + nt*8 + lr;
                uint32_t b0 = BsU[nrow*DSTR + kw0 + lc];
                uint32_t b1 = BsU[nrow*DSTR + kw0 + lc + 4];
                mma_f16(acc[0][nt], a[0], b0, b1);
                mma_f16(acc[1][nt], a[1], b0, b1);
            }
        }

#pragma unroll
        for (int mt = 0; mt < 2; mt++) {
            int r1 = t*64 + wm*32 + mt*16 + lr;
#pragma unroll
            for (int nt = 0; nt < 8; nt++) {
                int col = wn*64 + nt*8 + 2*lc;
                if (col < 128) {
                    if (r1 < n)
                        xlh[(size_t)r1*64 + (col>>1)] =
                            f2h2(acc[mt][nt][0] + bjx[nt], acc[mt][nt][1] + bjy[nt]);
                    if (r1 + 8 < n)
                        xlh[(size_t)(r1+8)*64 + (col>>1)] =
                            f2h2(acc[mt][nt][2] + bjx[nt], acc[mt][nt][3] + bjy[nt]);
                } else {
                    int c = col & 127;
                    if (r1 < n)
                        *(float2*)&outr[r1*128 + c] =
                            make_float2(acc[mt][nt][0] + bjx[nt], acc[mt][nt][1] + bjy[nt]);
                    if (r1 + 8 < n)
                        *(float2*)&outr[(r1+8)*128 + c] =
                            make_float2(acc[mt][nt][2] + bjx[nt], acc[mt][nt][3] + bjy[nt]);
                }
            }
        }

        cp_wait0();
        __syncthreads();
    }
}

// ---------------- fused GATv2 attention + softmax + aggregation (half2, 8-edge unroll) ----------------
__global__ __launch_bounds__(256) void gat_agg_kernel(
    const uint32_t* __restrict__ xlh, const float* __restrict__ xr,
    const int* __restrict__ rowptr, const int* __restrict__ adj,
    const uint32_t* __restrict__ relh, const float* __restrict__ att,
    const float* __restrict__ bias, float* __restrict__ out,
    uint32_t* __restrict__ xh, int n, int do_elu) {
    int warp = (blockIdx.x*blockDim.x + threadIdx.x) >> 5;
    if (warp >= n) return;
    unsigned lane = threadIdx.x & 31;
    unsigned lane2 = lane * 2;
    int c0 = lane * 4;

    const float4 attv = *(const float4*)&att[c0];
    const float4 xrv  = *(const float4*)&xr[warp*D + c0];
    const __half2 hatt0 = u2h(f2h2(attv.x, attv.y));
    const __half2 hatt1 = u2h(f2h2(attv.z, attv.w));
    const __half2 hxr0  = u2h(f2h2(xrv.x, xrv.y));
    const __half2 hxr1  = u2h(f2h2(xrv.z, xrv.w));
    const __half2 C06 = __floats2half2_rn(0.6f, 0.6f);
    const __half2 C04 = __floats2half2_rn(0.4f, 0.4f);

    float4 acc = make_float4(0.f, 0.f, 0.f, 0.f);
    float s = 0.f;

    int e0 = rowptr[warp], e1 = rowptr[warp+1];
    int e = e0;
    // 8-edge unrolled main loop (16 outstanding LDG.64)
    for (; e + 8 <= e1; e += 8) {
        int p[8];
        uint2 xw[8], rw[8];
#pragma unroll
        for (int i = 0; i < 8; i++) p[i] = __ldg(&adj[e+i]);
#pragma unroll
        for (int i = 0; i < 8; i++) {
            unsigned src = (unsigned)p[i] & 0xFFFFFu;
            unsigned t   = (unsigned)p[i] >> 20;
            xw[i] = ldnc2u(&xlh[src*64u + lane2]);
            rw[i] = *(const uint2*)&relh[t*64u + lane2];
        }
        float d[8];
#pragma unroll
        for (int i = 0; i < 8; i++) {
            __half2 m0 = __hadd2(u2h(xw[i].x), __hadd2(hxr0, u2h(rw[i].x)));
            __half2 m1 = __hadd2(u2h(xw[i].y), __hadd2(hxr1, u2h(rw[i].y)));
            __half2 l0 = __hfma2(m0, C06, __hmul2(__habs2(m0), C04));
            __half2 l1 = __hfma2(m1, C06, __hmul2(__habs2(m1), C04));
            __half2 dh = __hfma2(l1, hatt1, __hmul2(l0, hatt0));
            float2 df = __half22float2(dh);
            d[i] = df.x + df.y;
        }
        uint32_t q0 = f2h2(d[0], d[1]);
        uint32_t q1 = f2h2(d[2], d[3]);
        uint32_t q2 = f2h2(d[4], d[5]);
        uint32_t q3 = f2h2(d[6], d[7]);
#pragma unroll
        for (int off = 1; off <= 4; off <<= 1) {
            uint32_t t0 = __shfl_xor_sync(0xffffffffu, q0, off);
            uint32_t t1 = __shfl_xor_sync(0xffffffffu, q1, off);
            uint32_t t2 = __shfl_xor_sync(0xffffffffu, q2, off);
            uint32_t t3 = __shfl_xor_sync(0xffffffffu, q3, off);
            q0 = h2u(__hadd2(u2h(q0), u2h(t0)));
            q1 = h2u(__hadd2(u2h(q1), u2h(t1)));
            q2 = h2u(__hadd2(u2h(q2), u2h(t2)));
            q3 = h2u(__hadd2(u2h(q3), u2h(t3)));
        }
        float2 e01 = h22f2(q0), e23 = h22f2(q1), e45 = h22f2(q2), e67 = h22f2(q3);
        float w[8] = {__expf(e01.x), __expf(e01.y), __expf(e23.x), __expf(e23.y),
                      __expf(e45.x), __expf(e45.y), __expf(e67.x), __expf(e67.y)};
        s += ((w[0]+w[1]) + (w[2]+w[3])) + ((w[4]+w[5]) + (w[6]+w[7]));
#pragma unroll
        for (int i = 0; i < 8; i++) {
            float2 xl = h22f2(xw[i].x), xhp = h22f2(xw[i].y);
            acc.x = fmaf(w[i], xl.x,  acc.x);
            acc.y = fmaf(w[i], xl.y,  acc.y);
            acc.z = fmaf(w[i], xhp.x, acc.z);
            acc.w = fmaf(w[i], xhp.y, acc.w);
        }
    }
    for (; e < e1; e++) {
        int p0 = __ldg(&adj[e]);
        unsigned src = (unsigned)p0 & 0xFFFFFu;
        unsigned t   = (unsigned)p0 >> 20;
        uint2 xw = ldnc2u(&xlh[src*64u + lane2]);
        uint2 rw = *(const uint2*)&relh[t*64u + lane2];
        __half2 m0 = __hadd2(u2h(xw.x), __hadd2(hxr0, u2h(rw.x)));
        __half2 m1 = __hadd2(u2h(xw.y), __hadd2(hxr1, u2h(rw.y)));
        __half2 l0 = __hfma2(m0, C06, __hmul2(__habs2(m0), C04));
        __half2 l1 = __hfma2(m1, C06, __hmul2(__habs2(m1), C04));
        __half2 dh = __hfma2(l1, hatt1, __hmul2(l0, hatt0));
        float2 df = __half22float2(dh);
        float d0 = df.x + df.y;
        d0 += __shfl_xor_sync(0xffffffffu, d0, 1);
        d0 += __shfl_xor_sync(0xffffffffu, d0, 2);
        d0 += __shfl_xor_sync(0xffffffffu, d0, 4);
        float w0 = __expf(d0);
        s += w0;
        float2 xl = h22f2(xw.x), xhp = h22f2(xw.y);
        acc.x = fmaf(w0, xl.x,  acc.x);
        acc.y = fmaf(w0, xl.y,  acc.y);
        acc.z = fmaf(w0, xhp.x, acc.z);
        acc.w = fmaf(w0, xhp.y, acc.w);
    }

    float inv = (s > 0.f) ? (1.f / s) : 0.f;
    float4 bj = *(const float4*)&bias[c0];
    float4 r;
    r.x = fmaf(acc.x, inv, bj.x);
    r.y = fmaf(acc.y, inv, bj.y);
    r.z = fmaf(acc.z, inv, bj.z);
    r.w = fmaf(acc.w, inv, bj.w);
    if (do_elu) {
        r.x = (r.x > 0.f) ? r.x : (__expf(r.x) - 1.f);
        r.y = (r.y > 0.f) ? r.y : (__expf(r.y) - 1.f);
        r.z = (r.z > 0.f) ? r.z : (__expf(r.z) - 1.f);
        r.w = (r.w > 0.f) ? r.w : (__expf(r.w) - 1.f);
    }
    if (xh) {
        uint2 w = make_uint2(f2h2(r.x, r.y), f2h2(r.z, r.w));
        *(uint2*)&xh[(size_t)warp*64 + lane*2] = w;
    } else {
        *(float4*)&out[warp*D + c0] = r;
    }
}

// ---------------- launch ----------------
extern "C" void kernel_launch(void* const* d_in, const int* in_sizes, int n_in,
                              void* d_out, int out_size) {
    const int*   entity = (const int*)  d_in[0];
    const int*   eidx   = (const int*)  d_in[1];
    const int*   etype  = (const int*)  d_in[2];
    const float* nf     = (const float*)d_in[3];
    const float* rel    = (const float*)d_in[4];
    const float* pw     = (const float*)d_in[5];
    const float* pb     = (const float*)d_in[6];
    const float* wl     = (const float*)d_in[7];
    const float* bl     = (const float*)d_in[8];
    const float* wr     = (const float*)d_in[9];
    const float* brr    = (const float*)d_in[10];
    const float* we     = (const float*)d_in[11];
    const float* att    = (const float*)d_in[12];
    const float* bias   = (const float*)d_in[13];
    float* out = (float*)d_out;

    int n  = in_sizes[0];
    int e  = in_sizes[2];
    int Rn = in_sizes[4] / D;
    int F  = in_sizes[3] / n;
    const int* srcp = eidx;
    const int* dstp = eidx + e;

    float *pxr;
    uint32_t *pxlh, *pbst, *pbpj, *pxh, *prelh;
    int *prow, *pwoff, *padj, *ppart;
    cudaGetSymbolAddress((void**)&pxlh,  g_xlh);
    cudaGetSymbolAddress((void**)&pxr,   g_xr);
    cudaGetSymbolAddress((void**)&pxh,   g_xh);
    cudaGetSymbolAddress((void**)&prelh, g_relh);
    cudaGetSymbolAddress((void**)&pbst,  g_bstage);
    cudaGetSymbolAddress((void**)&pbpj,  g_bproj);
    cudaGetSymbolAddress((void**)&prow,  g_rowptr);
    cudaGetSymbolAddress((void**)&pwoff, g_woff);
    cudaGetSymbolAddress((void**)&padj,  g_adj);
    cudaGetSymbolAddress((void**)&ppart, g_partials);

    int nsm = 148;
    cudaDeviceGetAttribute(&nsm, cudaDevAttrMultiProcessorCount, 0);

    cudaFuncSetAttribute(proj_mma_kernel, cudaFuncAttributeMaxDynamicSharedMemorySize, PM_SMEM);
    cudaFuncSetAttribute(gemm_dual_mma_kernel, cudaFuncAttributeMaxDynamicSharedMemorySize, MMA_SMEM);

    int nTiles = (n + 63) / 64;
    int projGrid = (nTiles < 2*nsm) ? nTiles : 2*nsm;
    int dualGrid = (nTiles < 2*nsm) ? nTiles : 2*nsm;
    int aggBlocks = (n*32 + 255) / 256;
    int nb = (n + 1023) / 1024;

    cudaMemsetAsync(pwoff, 0, (size_t)n * sizeof(int));
    prep_bp_kernel<<<128, 160>>>(pw, pbpj, F);
    prep_b_kernel<<<dim3(256, LAYERS), 64>>>(wl, wr, pbst);
    proj_mma_kernel<<<projGrid, 256, PM_SMEM>>>(nf, entity, pbpj, pb, pxh, n, F, nTiles);
    gemm_dual_mma_kernel<<<dualGrid, 256, MMA_SMEM>>>(pxh, pbst, bl, brr,
                                                      pxlh, pxr, n, nTiles);
    relproj_kernel<<<dim3((Rn + 3)/4, LAYERS), 64>>>(rel, we, prelh, Rn);
    hist_kernel<<<(e+255)/256, 256>>>(dstp, pwoff, e);
    scan1_kernel<<<nb, 1024>>>(pwoff, prow, ppart, n);
    scan2_kernel<<<1, 128>>>(ppart, prow, nb, n, e);
    scan3_kernel<<<(n+255)/256, 256>>>(prow, ppart, pwoff, n);
    scatter_kernel<<<(e+255)/256, 256>>>(srcp, dstp, etype, pwoff, padj, e);

    // layer 0 aggregation -> fp16 x image (feeds dual L1)
    gat_agg_kernel<<<aggBlocks, 256>>>(pxlh, pxr, prow, padj, prelh, att, bias,
                                       out, pxh, n, 1);

    // layer 1
    gemm_dual_mma_kernel<<<dualGrid, 256, MMA_SMEM>>>(pxh, pbst + 16384, bl + D, brr + D,
                                                      pxlh, pxr, n, nTiles);
    gat_agg_kernel<<<aggBlocks, 256>>>(pxlh, pxr, prow, padj, prelh + Rn*64, att + D, bias + D,
                                       out, (uint32_t*)nullptr, n, 0);
}

// round 14
// speedup vs baseline: 1.1265x; 1.1265x over previous
#include <cuda_runtime.h>
#include <cuda_fp16.h>
#include <math.h>
#include <stdint.h>

#define D       128
#define NHEADS  4
#define MAXN    50048
#define MAXE    640000
#define MAXR    256
#define LAYERS  2

// fp16 dual GEMM: CTA tile M=64, N=256, A via cp.async from fp16 x image.
#define DSTR 68
#define DA_WORDS (2*64*DSTR)
#define DB_WORDS (256*DSTR)
#define MMA_SMEM ((DA_WORDS + DB_WORDS)*4)    // 104448 -> 2 CTAs/SM

// fp16 proj GEMM: CTA tile M=64, N=128, K=320 in 5 chunks of 64
#define PSTR 36
#define PM_A_WORDS (2*64*PSTR)
#define PM_B_WORDS (2*128*PSTR)
#define PM_SMEM ((PM_A_WORDS + PM_B_WORDS)*4) // 55296

// ---------------- helpers ----------------
__device__ __forceinline__ void cp_async16(unsigned saddr, const void* gaddr, int valid) {
    asm volatile("cp.async.ca.shared.global [%0], [%1], 16, %2;"
                 :: "r"(saddr), "l"(gaddr), "r"(valid ? 16 : 0));
}
__device__ __forceinline__ void cp_commit() { asm volatile("cp.async.commit_group;"); }
__device__ __forceinline__ void cp_wait0()  { asm volatile("cp.async.wait_group 0;"); }

__device__ __forceinline__ uint2 ldnc2u(const uint32_t* p) {
    uint2 v;
    asm volatile("ld.global.nc.L1::no_allocate.v2.u32 {%0,%1}, [%2];"
                 : "=r"(v.x), "=r"(v.y) : "l"(p));
    return v;
}

__device__ __forceinline__ uint32_t f2h2(float lo, float hi) {
    __half2 h = __floats2half2_rn(lo, hi);
    return *(uint32_t*)&h;
}
__device__ __forceinline__ float2 h22f2(uint32_t w) {
    return __half22float2(*(__half2*)&w);
}
__device__ __forceinline__ __half2 u2h(uint32_t w) { return *(__half2*)&w; }
__device__ __forceinline__ uint32_t h2u(__half2 h) { return *(uint32_t*)&h; }

// m16n8k16 fp16 MMA, fp32 accumulate
__device__ __forceinline__ void mma_f16(float* d, const uint32_t* a, uint32_t b0, uint32_t b1) {
    asm volatile(
        "mma.sync.aligned.m16n8k16.row.col.f32.f16.f16.f32 "
        "{%0,%1,%2,%3}, {%4,%5,%6,%7}, {%8,%9}, {%0,%1,%2,%3};"
        : "+f"(d[0]), "+f"(d[1]), "+f"(d[2]), "+f"(d[3])
        : "r"(a[0]), "r"(a[1]), "r"(a[2]), "r"(a[3]), "r"(b0), "r"(b1));
}

// ---------------- device scratch ----------------
__device__ uint32_t g_xlh[MAXN*64];           // fp16 x_l image [n][64 half2-words]
__device__ float    g_xr[MAXN*D];
__device__ uint32_t g_xh[MAXN*64];            // fp16 x image (GEMM A operand)
__device__ int      g_rowptr[MAXN+1];
__device__ int      g_woff[MAXN];
__device__ int      g_adj[MAXE];
__device__ int      g_partials[128];
__device__ uint32_t g_relh[LAYERS*MAXR*64];   // fp16 relproj image
__device__ uint32_t g_bstage[LAYERS*256*64];
__device__ uint32_t g_bproj[128*160];

// ---------------- CSR build ----------------
__global__ void hist_kernel(const int* __restrict__ dst, int* cnt, int e) {
    int i = blockIdx.x*blockDim.x + threadIdx.x;
    if (i < e) atomicAdd(&cnt[dst[i]], 1);
}

__global__ void scan1_kernel(const int* __restrict__ cnt, int* rowptr, int* partials, int n) {
    __shared__ int sh[1024];
    int i = blockIdx.x*1024 + threadIdx.x;
    int v = (i < n) ? cnt[i] : 0;
    sh[threadIdx.x] = v;
    __syncthreads();
    for (int off = 1; off < 1024; off <<= 1) {
        int t = (threadIdx.x >= off) ? sh[threadIdx.x - off] : 0;
        __syncthreads();
        sh[threadIdx.x] += t;
        __syncthreads();
    }
    if (i < n) rowptr[i] = sh[threadIdx.x] - v;
    if (threadIdx.x == 1023) partials[blockIdx.x] = sh[1023];
}

__global__ void scan2_kernel(int* partials, int* rowptr, int nb, int n, int total) {
    __shared__ int sh[128];
    int v = (threadIdx.x < nb) ? partials[threadIdx.x] : 0;
    sh[threadIdx.x] = v;
    __syncthreads();
    for (int off = 1; off < 128; off <<= 1) {
        int t = (threadIdx.x >= off) ? sh[threadIdx.x - off] : 0;
        __syncthreads();
        sh[threadIdx.x] += t;
        __syncthreads();
    }
    if (threadIdx.x < nb) partials[threadIdx.x] = sh[threadIdx.x] - v;
    if (threadIdx.x == 0) rowptr[n] = total;
}

__global__ void scan3_kernel(int* rowptr, const int* __restrict__ partials, int* woff, int n) {
    int i = blockIdx.x*blockDim.x + threadIdx.x;
    if (i < n) {
        int v = rowptr[i] + partials[i >> 10];
        rowptr[i] = v;
        woff[i] = v;
    }
}

__global__ void scatter_kernel(const int* __restrict__ src, const int* __restrict__ dst,
                               const int* __restrict__ etype, int* woff, int* adj, int e) {
    int i = blockIdx.x*blockDim.x + threadIdx.x;
    if (i < e) {
        int p = atomicAdd(&woff[dst[i]], 1);
        adj[p] = src[i] | (etype[i] << 20);
    }
}

// ---------------- rel_proj -> fp16 image ----------------
__global__ void relproj_kernel(const float* __restrict__ rel, const float* __restrict__ we,
                               uint32_t* __restrict__ outp, int Rn) {
    int r0 = blockIdx.x * 4, l = blockIdx.y, c2 = threadIdx.x;  // c2: 0..63
    __shared__ float sr[4][D];
#pragma unroll
    for (int j = 0; j < 8; j++) {
        int q = j*64 + c2;
        int row = q >> 7, ch = q & 127;
        int rr = r0 + row;
        sr[row][ch] = (rr < Rn) ? rel[rr*D + ch] : 0.f;
    }
    __syncthreads();
    const float* W = we + l*D*D;
    float a[4][2];
#pragma unroll
    for (int j = 0; j < 4; j++) { a[j][0] = 0.f; a[j][1] = 0.f; }
#pragma unroll 8
    for (int k = 0; k < D; k++) {
        float w0 = __ldg(&W[k*D + 2*c2]);
        float w1 = __ldg(&W[k*D + 2*c2 + 1]);
#pragma unroll
        for (int j = 0; j < 4; j++) {
            a[j][0] = fmaf(sr[j][k], w0, a[j][0]);
            a[j][1] = fmaf(sr[j][k], w1, a[j][1]);
        }
    }
#pragma unroll
    for (int j = 0; j < 4; j++)
        if (r0 + j < Rn)
            outp[(l*Rn + r0 + j)*64 + c2] = f2h2(a[j][0], a[j][1]);
}

// ---------------- B pre-stages (fp16 pairs) ----------------
__global__ void prep_b_kernel(const float* __restrict__ wl, const float* __restrict__ wr,
                              uint32_t* __restrict__ gB) {
    int nrow = blockIdx.x, l = blockIdx.y, kw = threadIdx.x;
    int c = nrow & 127;
    const float* W = (nrow < 128) ? (wl + l*D*D) : (wr + l*D*D);
    gB[l*16384 + nrow*64 + kw] = f2h2(W[(2*kw)*D + c], W[(2*kw+1)*D + c]);
}

__global__ void prep_bp_kernel(const float* __restrict__ pw, uint32_t* __restrict__ gBp, int F) {
    int nrow = blockIdx.x;
    int kw = threadIdx.x;
    float v0 = (2*kw     < F) ? pw[(2*kw)*128 + nrow]     : 0.f;
    float v1 = (2*kw + 1 < F) ? pw[(2*kw + 1)*128 + nrow] : 0.f;
    gBp[nrow*160 + kw] = f2h2(v0, v1);
}

// ---------------- fp16 proj GEMM -> writes fp16 x image ----------------
__global__ __launch_bounds__(256, 2) void proj_mma_kernel(
    const float* __restrict__ nf, const int* __restrict__ entity,
    const uint32_t* __restrict__ gBp, const float* __restrict__ pb,
    uint32_t* __restrict__ xh, int n, int F, int nTiles) {
    extern __shared__ uint32_t smu[];
    uint32_t* AsU = smu;
    uint32_t* BsU = smu + PM_A_WORDS;
    int tid = threadIdx.x, lane = tid & 31, wid = tid >> 5;
    int wm = wid >> 2, wn = wid & 3;
    int lr = lane >> 2, lc = lane & 3;

    unsigned bbase = (unsigned)__cvta_generic_to_shared(BsU);

    float bjx[4], bjy[4];
#pragma unroll
    for (int nt = 0; nt < 4; nt++) {
        int col = wn*32 + nt*8 + 2*lc;
        bjx[nt] = pb[col];
        bjy[nt] = pb[col+1];
    }

    float4 aReg[4];
    auto loadA = [&](int t, int c) {
#pragma unroll
        for (int j = 0; j < 4; j++) {
            int q = tid + j*256;
            int r = q >> 4, k4 = q & 15;
            int gr = t*64 + r;
            int kg = c*64 + k4*4;
            aReg[j] = (gr < n && kg < F)
                ? *(const float4*)&nf[(long long)entity[gr]*F + kg]
                : make_float4(0,0,0,0);
        }
    };
    auto stsA = [&](int buf) {
#pragma unroll
        for (int j = 0; j < 4; j++) {
            int q = tid + j*256;
            int r = q >> 4, k4 = q & 15;
            uint2 w = make_uint2(f2h2(aReg[j].x, aReg[j].y), f2h2(aReg[j].z, aReg[j].w));
            *(uint2*)&AsU[buf*64*PSTR + r*PSTR + k4*2] = w;
        }
    };
    auto issueB = [&](int c, int buf) {
#pragma unroll
        for (int j = 0; j < 4; j++) {
            int q = tid + j*256;
            int row = q >> 3, seg = q & 7;
            cp_async16(bbase + (buf*128*PSTR + row*PSTR + seg*4)*4,
                       gBp + row*160 + c*32 + seg*4, 1);
        }
        cp_commit();
    };

    int tile0 = blockIdx.x;
    loadA(tile0, 0);
    issueB(0, 0);
    stsA(0);
    cp_wait0();
    __syncthreads();

    int buf = 0;
    for (int t = tile0; t < nTiles; t += gridDim.x) {
        float acc[2][4][4];
#pragma unroll
        for (int mt = 0; mt < 2; mt++)
#pragma unroll
            for (int nt = 0; nt < 4; nt++)
#pragma unroll
                for (int i = 0; i < 4; i++) acc[mt][nt][i] = 0.f;

#pragma unroll
        for (int c = 0; c < 5; c++) {
            int tn = (c < 4) ? t : t + gridDim.x;
            int cn = (c < 4) ? c + 1 : 0;
            bool hasNext = (c < 4) || (tn < nTiles);
            if (hasNext) { loadA(tn, cn); issueB(cn, buf ^ 1); }

            const uint32_t* Ab = &AsU[buf*64*PSTR];
            const uint32_t* Bb = &BsU[buf*128*PSTR];
#pragma unroll
            for (int kk = 0; kk < 4; kk++) {
                int kw0 = kk*8;
                uint32_t a[2][4];
#pragma unroll
                for (int mt = 0; mt < 2; mt++) {
                    int r = wm*32 + mt*16 + lr;
                    a[mt][0] = Ab[r*PSTR + kw0 + lc];
                    a[mt][1] = Ab[(r+8)*PSTR + kw0 + lc];
                    a[mt][2] = Ab[r*PSTR + kw0 + lc + 4];
                    a[mt][3] = Ab[(r+8)*PSTR + kw0 + lc + 4];
                }
#pragma unroll
                for (int nt = 0; nt < 4; nt++) {
                    int nrow = wn*32 + nt*8 + lr;
                    uint32_t b0 = Bb[nrow*PSTR + kw0 + lc];
                    uint32_t b1 = Bb[nrow*PSTR + kw0 + lc + 4];
                    mma_f16(acc[0][nt], a[0], b0, b1);
                    mma_f16(acc[1][nt], a[1], b0, b1);
                }
            }

            if (c == 4) {
#pragma unroll
                for (int mt = 0; mt < 2; mt++) {
                    int r1 = t*64 + wm*32 + mt*16 + lr;
#pragma unroll
                    for (int nt = 0; nt < 4; nt++) {
                        int col = wn*32 + nt*8 + 2*lc;
                        if (r1 < n)
                            xh[(size_t)r1*64 + (col>>1)] =
                                f2h2(acc[mt][nt][0] + bjx[nt], acc[mt][nt][1] + bjy[nt]);
                        if (r1 + 8 < n)
                            xh[(size_t)(r1+8)*64 + (col>>1)] =
                                f2h2(acc[mt][nt][2] + bjx[nt], acc[mt][nt][3] + bjy[nt]);
                    }
                }
            }

            if (hasNext) stsA(buf ^ 1);
            cp_wait0();
            __syncthreads();
            buf ^= 1;
        }
    }
}

// ---------------- fp16 dual GEMM: CTA 64x256, A via cp.async from xh ----------------
__global__ __launch_bounds__(256, 2) void gemm_dual_mma_kernel(
    const uint32_t* __restrict__ xh, const uint32_t* __restrict__ gB,
    const float* __restrict__ bl, const float* __restrict__ br,
    uint32_t* __restrict__ xlh, float* __restrict__ outr, int n, int nTiles) {
    extern __shared__ uint32_t smu[];
    uint32_t* AsU = smu;
    uint32_t* BsU = smu + DA_WORDS;
    int tid = threadIdx.x, lane = tid & 31, wid = tid >> 5;
    int wm = wid >> 2, wn = wid & 3;
    int lr = lane >> 2, lc = lane & 3;

    unsigned abase = (unsigned)__cvta_generic_to_shared(AsU);

    {
        unsigned bbase = (unsigned)__cvta_generic_to_shared(BsU);
#pragma unroll
        for (int j = 0; j < 16; j++) {
            int q = tid + j*256;
            int row = q >> 4, seg = q & 15;
            cp_async16(bbase + (row*DSTR + seg*4)*4, gB + row*64 + seg*4, 1);
        }
    }

    auto issueA = [&](int t, int buf) {
#pragma unroll
        for (int j = 0; j < 4; j++) {
            int q = tid + j*256;
            int row = q >> 4, seg = q & 15;
            cp_async16(abase + (buf*64*DSTR + row*DSTR + seg*4)*4,
                       xh + (size_t)(t*64 + row)*64 + seg*4, 1);
        }
        cp_commit();
    };

    float bjx[8], bjy[8];
#pragma unroll
    for (int nt = 0; nt < 8; nt++) {
        int col = wn*64 + nt*8 + 2*lc;
        const float* bv = (col < 128) ? bl : br;
        int c = col & 127;
        bjx[nt] = bv[c];
        bjy[nt] = bv[c+1];
    }

    int tile0 = blockIdx.x;
    issueA(tile0, 0);
    cp_wait0();
    __syncthreads();

    int buf = 0;
    for (int t = tile0; t < nTiles; t += gridDim.x, buf ^= 1) {
        int tn = t + gridDim.x;
        if (tn < nTiles) issueA(tn, buf ^ 1);

        float acc[2][8][4];
#pragma unroll
        for (int mt = 0; mt < 2; mt++)
#pragma unroll
            for (int nt = 0; nt < 8; nt++)
#pragma unroll
                for (int i = 0; i < 4; i++) acc[mt][nt][i] = 0.f;

        const uint32_t* Ab = &AsU[buf*64*DSTR];
#pragma unroll
        for (int kk = 0; kk < 8; kk++) {
            int kw0 = kk*8;
            uint32_t a[2][4];
#pragma unroll
            for (int mt = 0; mt < 2; mt++) {
                int r = wm*32 + mt*16 + lr;
                a[mt][0] = Ab[r*DSTR + kw0 + lc];
                a[mt][1] = Ab[(r+8)*DSTR + kw0 + lc];
                a[mt][2] = Ab[r*DSTR + kw0 + lc + 4];
                a[mt][3] = Ab[(r+8)*DSTR + kw0 + lc + 4];
            }
#pragma unroll
            for (int nt = 0; nt < 8; nt++) {
                int nrow = wn*64 + nt*8 + lr;
                uint32_t b0 = BsU[nrow*DSTR + kw0 + lc];
                uint32_t b1 = BsU[nrow*DSTR + kw0 + lc + 4];
                mma_f16(acc[0][nt], a[0], b0, b1);
                mma_f16(acc[1][nt], a[1], b0, b1);
            }
        }

#pragma unroll
        for (int mt = 0; mt < 2; mt++) {
            int r1 = t*64 + wm*32 + mt*16 + lr;
#pragma unroll
            for (int nt = 0; nt < 8; nt++) {
                int col = wn*64 + nt*8 + 2*lc;
                if (col < 128) {
                    if (r1 < n)
                        xlh[(size_t)r1*64 + (col>>1)] =
                            f2h2(acc[mt][nt][0] + bjx[nt], acc[mt][nt][1] + bjy[nt]);
                    if (r1 + 8 < n)
                        xlh[(size_t)(r1+8)*64 + (col>>1)] =
                            f2h2(acc[mt][nt][2] + bjx[nt], acc[mt][nt][3] + bjy[nt]);
                } else {
                    int c = col & 127;
                    if (r1 < n)
                        *(float2*)&outr[r1*128 + c] =
                            make_float2(acc[mt][nt][0] + bjx[nt], acc[mt][nt][1] + bjy[nt]);
                    if (r1 + 8 < n)
                        *(float2*)&outr[(r1+8)*128 + c] =
                            make_float2(acc[mt][nt][2] + bjx[nt], acc[mt][nt][3] + bjy[nt]);
                }
            }
        }

        cp_wait0();
        __syncthreads();
    }
}

// ---------------- fused GATv2 attention + softmax + aggregation (half2, 4-edge) ----------------
__global__ __launch_bounds__(256) void gat_agg_kernel(
    const uint32_t* __restrict__ xlh, const float* __restrict__ xr,
    const int* __restrict__ rowptr, const int* __restrict__ adj,
    const uint32_t* __restrict__ relh, const float* __restrict__ att,
    const float* __restrict__ bias, float* __restrict__ out,
    uint32_t* __restrict__ xh, int n, int do_elu) {
    int warp = (blockIdx.x*blockDim.x + threadIdx.x) >> 5;
    if (warp >= n) return;
    unsigned lane = threadIdx.x & 31;
    unsigned lane2 = lane * 2;
    int c0 = lane * 4;

    const float4 attv = *(const float4*)&att[c0];
    const float4 xrv  = *(const float4*)&xr[warp*D + c0];
    const __half2 hatt0 = u2h(f2h2(attv.x, attv.y));
    const __half2 hatt1 = u2h(f2h2(attv.z, attv.w));
    const __half2 hxr0  = u2h(f2h2(xrv.x, xrv.y));
    const __half2 hxr1  = u2h(f2h2(xrv.z, xrv.w));
    const __half2 C06 = __floats2half2_rn(0.6f, 0.6f);
    const __half2 C04 = __floats2half2_rn(0.4f, 0.4f);

    float4 acc = make_float4(0.f, 0.f, 0.f, 0.f);
    float s = 0.f;

    int e0 = rowptr[warp], e1 = rowptr[warp+1];
    int e = e0;
    for (; e + 4 <= e1; e += 4) {
        int p[4];
        uint2 xw[4], rw[4];
#pragma unroll
        for (int i = 0; i < 4; i++) p[i] = __ldg(&adj[e+i]);
#pragma unroll
        for (int i = 0; i < 4; i++) {
            unsigned src = (unsigned)p[i] & 0xFFFFFu;
            unsigned t   = (unsigned)p[i] >> 20;
            xw[i] = ldnc2u(&xlh[src*64u + lane2]);
            rw[i] = *(const uint2*)&relh[t*64u + lane2];
        }
        float d[4];
#pragma unroll
        for (int i = 0; i < 4; i++) {
            __half2 m0 = __hadd2(u2h(xw[i].x), __hadd2(hxr0, u2h(rw[i].x)));
            __half2 m1 = __hadd2(u2h(xw[i].y), __hadd2(hxr1, u2h(rw[i].y)));
            __half2 l0 = __hfma2(m0, C06, __hmul2(__habs2(m0), C04));
            __half2 l1 = __hfma2(m1, C06, __hmul2(__habs2(m1), C04));
            __half2 dh = __hfma2(l1, hatt1, __hmul2(l0, hatt0));
            float2 df = __half22float2(dh);
            d[i] = df.x + df.y;
        }
        uint32_t q0 = f2h2(d[0], d[1]);
        uint32_t q1 = f2h2(d[2], d[3]);
#pragma unroll
        for (int off = 1; off <= 4; off <<= 1) {
            uint32_t t0 = __shfl_xor_sync(0xffffffffu, q0, off);
            uint32_t t1 = __shfl_xor_sync(0xffffffffu, q1, off);
            q0 = h2u(__hadd2(u2h(q0), u2h(t0)));
            q1 = h2u(__hadd2(u2h(q1), u2h(t1)));
        }
        float2 e01 = h22f2(q0), e23 = h22f2(q1);
        float w0 = __expf(e01.x), w1 = __expf(e01.y);
        float w2 = __expf(e23.x), w3 = __expf(e23.y);
        s += (w0 + w1) + (w2 + w3);
        float2 x0l = h22f2(xw[0].x), x0h = h22f2(xw[0].y);
        float2 x1l = h22f2(xw[1].x), x1h = h22f2(xw[1].y);
        float2 x2l = h22f2(xw[2].x), x2h = h22f2(xw[2].y);
        float2 x3l = h22f2(xw[3].x), x3h = h22f2(xw[3].y);
        acc.x += fmaf(w0, x0l.x, w1*x1l.x) + fmaf(w2, x2l.x, w3*x3l.x);
        acc.y += fmaf(w0, x0l.y, w1*x1l.y) + fmaf(w2, x2l.y, w3*x3l.y);
        acc.z += fmaf(w0, x0h.x, w1*x1h.x) + fmaf(w2, x2h.x, w3*x3h.x);
        acc.w += fmaf(w0, x0h.y, w1*x1h.y) + fmaf(w2, x2h.y, w3*x3h.y);
    }
    for (; e < e1; e++) {
        int p0 = __ldg(&adj[e]);
        unsigned src = (unsigned)p0 & 0xFFFFFu;
        unsigned t   = (unsigned)p0 >> 20;
        uint2 xw = ldnc2u(&xlh[src*64u + lane2]);
        uint2 rw = *(const uint2*)&relh[t*64u + lane2];
        __half2 m0 = __hadd2(u2h(xw.x), __hadd2(hxr0, u2h(rw.x)));
        __half2 m1 = __hadd2(u2h(xw.y), __hadd2(hxr1, u2h(rw.y)));
        __half2 l0 = __hfma2(m0, C06, __hmul2(__habs2(m0), C04));
        __half2 l1 = __hfma2(m1, C06, __hmul2(__habs2(m1), C04));
        __half2 dh = __hfma2(l1, hatt1, __hmul2(l0, hatt0));
        float2 df = __half22float2(dh);
        float d0 = df.x + df.y;
        d0 += __shfl_xor_sync(0xffffffffu, d0, 1);
        d0 += __shfl_xor_sync(0xffffffffu, d0, 2);
        d0 += __shfl_xor_sync(0xffffffffu, d0, 4);
        float w0 = __expf(d0);
        s += w0;
        float2 xl = h22f2(xw.x), xhp = h22f2(xw.y);
        acc.x = fmaf(w0, xl.x,  acc.x);
        acc.y = fmaf(w0, xl.y,  acc.y);
        acc.z = fmaf(w0, xhp.x, acc.z);
        acc.w = fmaf(w0, xhp.y, acc.w);
    }

    float inv = (s > 0.f) ? (1.f / s) : 0.f;
    float4 bj = *(const float4*)&bias[c0];
    float4 r;
    r.x = fmaf(acc.x, inv, bj.x);
    r.y = fmaf(acc.y, inv, bj.y);
    r.z = fmaf(acc.z, inv, bj.z);
    r.w = fmaf(acc.w, inv, bj.w);
    if (do_elu) {
        r.x = (r.x > 0.f) ? r.x : (__expf(r.x) - 1.f);
        r.y = (r.y > 0.f) ? r.y : (__expf(r.y) - 1.f);
        r.z = (r.z > 0.f) ? r.z : (__expf(r.z) - 1.f);
        r.w = (r.w > 0.f) ? r.w : (__expf(r.w) - 1.f);
    }
    if (xh) {
        uint2 w = make_uint2(f2h2(r.x, r.y), f2h2(r.z, r.w));
        *(uint2*)&xh[(size_t)warp*64 + lane*2] = w;
    } else {
        *(float4*)&out[warp*D + c0] = r;
    }
}

// ---------------- launch ----------------
extern "C" void kernel_launch(void* const* d_in, const int* in_sizes, int n_in,
                              void* d_out, int out_size) {
    const int*   entity = (const int*)  d_in[0];
    const int*   eidx   = (const int*)  d_in[1];
    const int*   etype  = (const int*)  d_in[2];
    const float* nf     = (const float*)d_in[3];
    const float* rel    = (const float*)d_in[4];
    const float* pw     = (const float*)d_in[5];
    const float* pb     = (const float*)d_in[6];
    const float* wl     = (const float*)d_in[7];
    const float* bl     = (const float*)d_in[8];
    const float* wr     = (const float*)d_in[9];
    const float* brr    = (const float*)d_in[10];
    const float* we     = (const float*)d_in[11];
    const float* att    = (const float*)d_in[12];
    const float* bias   = (const float*)d_in[13];
    float* out = (float*)d_out;

    int n  = in_sizes[0];
    int e  = in_sizes[2];
    int Rn = in_sizes[4] / D;
    int F  = in_sizes[3] / n;
    const int* srcp = eidx;
    const int* dstp = eidx + e;

    float *pxr;
    uint32_t *pxlh, *pbst, *pbpj, *pxh, *prelh;
    int *prow, *pwoff, *padj, *ppart;
    cudaGetSymbolAddress((void**)&pxlh,  g_xlh);
    cudaGetSymbolAddress((void**)&pxr,   g_xr);
    cudaGetSymbolAddress((void**)&pxh,   g_xh);
    cudaGetSymbolAddress((void**)&prelh, g_relh);
    cudaGetSymbolAddress((void**)&pbst,  g_bstage);
    cudaGetSymbolAddress((void**)&pbpj,  g_bproj);
    cudaGetSymbolAddress((void**)&prow,  g_rowptr);
    cudaGetSymbolAddress((void**)&pwoff, g_woff);
    cudaGetSymbolAddress((void**)&padj,  g_adj);
    cudaGetSymbolAddress((void**)&ppart, g_partials);

    int nsm = 148;
    cudaDeviceGetAttribute(&nsm, cudaDevAttrMultiProcessorCount, 0);

    cudaFuncSetAttribute(proj_mma_kernel, cudaFuncAttributeMaxDynamicSharedMemorySize, PM_SMEM);
    cudaFuncSetAttribute(gemm_dual_mma_kernel, cudaFuncAttributeMaxDynamicSharedMemorySize, MMA_SMEM);

    // side stream (created once, outside capture)
    static cudaStream_t s2 = nullptr;
    static cudaEvent_t evF = nullptr, evJ = nullptr;
    if (s2 == nullptr) {
        cudaStreamCreateWithFlags(&s2, cudaStreamNonBlocking);
        cudaEventCreateWithFlags(&evF, cudaEventDisableTiming);
        cudaEventCreateWithFlags(&evJ, cudaEventDisableTiming);
    }

    int nTiles = (n + 63) / 64;
    int projGrid = (nTiles < 2*nsm) ? nTiles : 2*nsm;
    int dualGrid = (nTiles < 2*nsm) ? nTiles : 2*nsm;
    int aggBlocks = (n*32 + 255) / 256;
    int nb = (n + 1023) / 1024;

    // fork: CSR build + relproj on s2; GEMM chain on main stream
    cudaEventRecord(evF, 0);
    cudaStreamWaitEvent(s2, evF, 0);

    cudaMemsetAsync(pwoff, 0, (size_t)n * sizeof(int), s2);
    hist_kernel<<<(e+255)/256, 256, 0, s2>>>(dstp, pwoff, e);
    scan1_kernel<<<nb, 1024, 0, s2>>>(pwoff, prow, ppart, n);
    scan2_kernel<<<1, 128, 0, s2>>>(ppart, prow, nb, n, e);
    scan3_kernel<<<(n+255)/256, 256, 0, s2>>>(prow, ppart, pwoff, n);
    scatter_kernel<<<(e+255)/256, 256, 0, s2>>>(srcp, dstp, etype, pwoff, padj, e);
    relproj_kernel<<<dim3((Rn + 3)/4, LAYERS), 64, 0, s2>>>(rel, we, prelh, Rn);
    cudaEventRecord(evJ, s2);

    // main stream: GEMM chain
    prep_bp_kernel<<<128, 160>>>(pw, pbpj, F);
    prep_b_kernel<<<dim3(256, LAYERS), 64>>>(wl, wr, pbst);
    proj_mma_kernel<<<projGrid, 256, PM_SMEM>>>(nf, entity, pbpj, pb, pxh, n, F, nTiles);
    gemm_dual_mma_kernel<<<dualGrid, 256, MMA_SMEM>>>(pxh, pbst, bl, brr,
                                                      pxlh, pxr, n, nTiles);

    // join: agg needs CSR + relproj
    cudaStreamWaitEvent(0, evJ, 0);

    // layer 0 aggregation -> fp16 x image (feeds dual L1)
    gat_agg_kernel<<<aggBlocks, 256>>>(pxlh, pxr, prow, padj, prelh, att, bias,
                                       out, pxh, n, 1);

    // layer 1
    gemm_dual_mma_kernel<<<dualGrid, 256, MMA_SMEM>>>(pxh, pbst + 16384, bl + D, brr + D,
                                                      pxlh, pxr, n, nTiles);
    gat_agg_kernel<<<aggBlocks, 256>>>(pxlh, pxr, prow, padj, prelh + Rn*64, att + D, bias + D,
                                       out, (uint32_t*)nullptr, n, 0);
}